// round 2
// baseline (speedup 1.0000x reference)
#include <cuda_runtime.h>
#include <cstdint>

#define B_   2
#define S_   2048
#define D_   1024
#define H_   16
#define DK_  64
#define DFF_ 4096
#define ROWS (B_*S_)   // 4096

// ---------------- scratch (device globals; no allocations allowed) ----------
__device__ float g_bufA[ROWS*D_];   // nx  -> ctx
__device__ float g_q  [ROWS*D_];    // q   -> x1
__device__ float g_k  [ROWS*D_];    // k   -> nx2
__device__ float g_v  [ROWS*D_];
__device__ float g_h  [ROWS*DFF_];  // ffn hidden

// ---------------- packed f32x2 helpers (Blackwell FFMA2 path) ---------------
__device__ __forceinline__ unsigned long long ffma2(unsigned long long a,
                                                    unsigned long long b,
                                                    unsigned long long c) {
    unsigned long long d;
    asm("fma.rn.f32x2 %0, %1, %2, %3;" : "=l"(d) : "l"(a), "l"(b), "l"(c));
    return d;
}
__device__ __forceinline__ unsigned long long fmul2(unsigned long long a,
                                                    unsigned long long b) {
    unsigned long long d;
    asm("mul.rn.f32x2 %0, %1, %2;" : "=l"(d) : "l"(a), "l"(b));
    return d;
}
__device__ __forceinline__ unsigned long long pack2(float x) {
    unsigned long long r;
    asm("mov.b64 %0, {%1, %1};" : "=l"(r) : "f"(x));
    return r;
}
__device__ __forceinline__ float2 unpack2(unsigned long long v) {
    float2 f;
    asm("mov.b64 {%0, %1}, %2;" : "=f"(f.x), "=f"(f.y) : "l"(v));
    return f;
}

// ---------------- LayerNorm: one 256-thread block per row (D=1024) ----------
__global__ __launch_bounds__(256) void ln_kernel(
    const float* __restrict__ x, const float* __restrict__ g,
    const float* __restrict__ bta, float* __restrict__ out)
{
    const int row = blockIdx.x;
    const int t   = threadIdx.x;
    const float4* xr = (const float4*)(x + (size_t)row * D_);
    float4 v = xr[t];
    float s  = v.x + v.y + v.z + v.w;
    float s2 = v.x*v.x + v.y*v.y + v.z*v.z + v.w*v.w;
    #pragma unroll
    for (int o = 16; o > 0; o >>= 1) {
        s  += __shfl_xor_sync(0xffffffffu, s,  o);
        s2 += __shfl_xor_sync(0xffffffffu, s2, o);
    }
    __shared__ float rs[8], rs2[8];
    const int w = t >> 5;
    if ((t & 31) == 0) { rs[w] = s; rs2[w] = s2; }
    __syncthreads();
    s = 0.f; s2 = 0.f;
    #pragma unroll
    for (int i = 0; i < 8; i++) { s += rs[i]; s2 += rs2[i]; }
    const float mu   = s * (1.0f / D_);
    const float var  = s2 * (1.0f / D_) - mu * mu;
    const float rstd = rsqrtf(var + 1e-5f);
    float4 gg = ((const float4*)g)[t];
    float4 bb = ((const float4*)bta)[t];
    float4 o4;
    o4.x = (v.x - mu) * rstd * gg.x + bb.x;
    o4.y = (v.y - mu) * rstd * gg.y + bb.y;
    o4.z = (v.z - mu) * rstd * gg.z + bb.z;
    o4.w = (v.w - mu) * rstd * gg.w + bb.w;
    ((float4*)(out + (size_t)row * D_))[t] = o4;
}

// ---------------- SGEMM-NT with packed f32x2 accumulators -------------------
// C[M,N] = A[M,K] * Bw[N,K]^T + bias[N]  (+ residual / gelu per EPI)
#define BM  128
#define BN  128
#define BKT 16

enum { EPI_NONE = 0, EPI_RES = 1, EPI_GELU = 2 };

template <int EPI>
__global__ __launch_bounds__(256) void sgemm_nt(
    int M, int N, int K,
    const float* __restrict__ A, const float* __restrict__ Bw,
    const float* __restrict__ bias, const float* __restrict__ resid,
    float* __restrict__ C)
{
    __shared__ __align__(16) float As[BKT][BM + 4];
    __shared__ __align__(16) float Bs[BKT][BN + 4];

    const int tid = threadIdx.x;
    const int tc  = tid & 15;   // 0..15 -> N
    const int tr  = tid >> 4;   // 0..15 -> M
    const float* Ab = A  + (size_t)blockIdx.y * BM * K;
    const float* Bb = Bw + (size_t)blockIdx.x * BN * K;
    const int lr = tid >> 2;          // 0..63
    const int lc = (tid & 3) * 4;     // 0,4,8,12

    float4 ldA[2], ldB[2];
    #pragma unroll
    for (int p = 0; p < 2; p++) {
        ldA[p] = *(const float4*)&Ab[(size_t)(lr + p * 64) * K + lc];
        ldB[p] = *(const float4*)&Bb[(size_t)(lr + p * 64) * K + lc];
    }

    unsigned long long acc[8][4];
    #pragma unroll
    for (int i = 0; i < 8; i++)
        #pragma unroll
        for (int j = 0; j < 4; j++) acc[i][j] = 0ull;

    for (int k0 = 0; k0 < K; k0 += BKT) {
        #pragma unroll
        for (int p = 0; p < 2; p++) {
            const int r = lr + p * 64;
            As[lc+0][r] = ldA[p].x; As[lc+1][r] = ldA[p].y;
            As[lc+2][r] = ldA[p].z; As[lc+3][r] = ldA[p].w;
            Bs[lc+0][r] = ldB[p].x; Bs[lc+1][r] = ldB[p].y;
            Bs[lc+2][r] = ldB[p].z; Bs[lc+3][r] = ldB[p].w;
        }
        __syncthreads();
        if (k0 + BKT < K) {
            #pragma unroll
            for (int p = 0; p < 2; p++) {
                ldA[p] = *(const float4*)&Ab[(size_t)(lr + p*64) * K + k0 + BKT + lc];
                ldB[p] = *(const float4*)&Bb[(size_t)(lr + p*64) * K + k0 + BKT + lc];
            }
        }
        #pragma unroll
        for (int kk = 0; kk < BKT; kk++) {
            float4 a0 = *(const float4*)&As[kk][tr * 8];
            float4 a1 = *(const float4*)&As[kk][tr * 8 + 4];
            ulonglong2 b0 = *(const ulonglong2*)&Bs[kk][tc * 8];
            ulonglong2 b1 = *(const ulonglong2*)&Bs[kk][tc * 8 + 4];
            const float am[8] = {a0.x, a0.y, a0.z, a0.w, a1.x, a1.y, a1.z, a1.w};
            #pragma unroll
            for (int i = 0; i < 8; i++) {
                const unsigned long long ap = pack2(am[i]);
                acc[i][0] = ffma2(ap, b0.x, acc[i][0]);
                acc[i][1] = ffma2(ap, b0.y, acc[i][1]);
                acc[i][2] = ffma2(ap, b1.x, acc[i][2]);
                acc[i][3] = ffma2(ap, b1.y, acc[i][3]);
            }
        }
        __syncthreads();
    }

    const int gc0 = blockIdx.x * BN + tc * 8;
    float bv[8];
    #pragma unroll
    for (int j = 0; j < 8; j++) bv[j] = bias[gc0 + j];

    #pragma unroll
    for (int i = 0; i < 8; i++) {
        const int grow = blockIdx.y * BM + tr * 8 + i;
        const size_t base = (size_t)grow * N + gc0;
        float v[8];
        #pragma unroll
        for (int j4 = 0; j4 < 4; j4++) {
            float2 f = unpack2(acc[i][j4]);
            v[2*j4]   = f.x + bv[2*j4];
            v[2*j4+1] = f.y + bv[2*j4+1];
        }
        if (EPI == EPI_RES) {
            float4 r0 = *(const float4*)&resid[base];
            float4 r1 = *(const float4*)&resid[base + 4];
            v[0]+=r0.x; v[1]+=r0.y; v[2]+=r0.z; v[3]+=r0.w;
            v[4]+=r1.x; v[5]+=r1.y; v[6]+=r1.z; v[7]+=r1.w;
        }
        if (EPI == EPI_GELU) {
            #pragma unroll
            for (int j = 0; j < 8; j++)
                v[j] = 0.5f * v[j] * (1.0f + erff(v[j] * 0.70710678118654752f));
        }
        *(float4*)&C[base]     = make_float4(v[0], v[1], v[2], v[3]);
        *(float4*)&C[base + 4] = make_float4(v[4], v[5], v[6], v[7]);
    }
}

// ---------------- flash-style attention -------------------------------------
// grid (S/64, H, B), 64 threads; each thread owns one query row entirely.
// MASK IS int32 (harness materializes jax bool as int32).
__global__ __launch_bounds__(64) void attn_kernel(
    const float* __restrict__ Q, const float* __restrict__ Kg,
    const float* __restrict__ Vg, const int* __restrict__ mask,
    float* __restrict__ O)
{
    const int b = blockIdx.z, h = blockIdx.y;
    const int t = threadIdx.x;
    const int q = blockIdx.x * 64 + t;

    __shared__ __align__(16) float Ks[32][64];
    __shared__ __align__(16) float Vs[32][64];
    float4* ksp = reinterpret_cast<float4*>(&Ks[0][0]);
    float4* vsp = reinterpret_cast<float4*>(&Vs[0][0]);

    unsigned long long q2[32], o2[32];
    {
        const ulonglong2* qp =
            (const ulonglong2*)(Q + ((size_t)(b * S_ + q)) * D_ + h * DK_);
        #pragma unroll
        for (int i = 0; i < 16; i++) {
            ulonglong2 qv = qp[i];
            q2[2*i] = qv.x; q2[2*i+1] = qv.y;
        }
    }
    #pragma unroll
    for (int i = 0; i < 32; i++) o2[i] = 0ull;

    float m = -3.0e38f, l = 0.f;
    const int* mrow = mask + ((size_t)(b * S_ + q)) * S_;

    for (int kt = 0; kt < S_; kt += 32) {
        #pragma unroll
        for (int i = 0; i < 8; i++) {
            const int f4 = i * 64 + t;
            const int j = f4 >> 4, d4 = f4 & 15;
            const size_t gi = ((size_t)(b * S_ + kt + j)) * D_ + h * DK_ + d4 * 4;
            ksp[f4] = *(const float4*)&Kg[gi];
            vsp[f4] = *(const float4*)&Vg[gi];
        }
        __syncthreads();

        int mw[32];
        #pragma unroll
        for (int i = 0; i < 8; i++)
            *(int4*)&mw[i * 4] = *(const int4*)(mrow + kt + i * 4);

        float sc[32];
        #pragma unroll
        for (int j = 0; j < 32; j++) {
            const ulonglong2* kp = (const ulonglong2*)Ks[j];
            unsigned long long a2 = 0ull, c2 = 0ull;
            #pragma unroll
            for (int d = 0; d < 16; d++) {
                ulonglong2 kv = kp[d];
                a2 = ffma2(q2[2*d],   kv.x, a2);
                c2 = ffma2(q2[2*d+1], kv.y, c2);
            }
            float2 fa = unpack2(a2), fc = unpack2(c2);
            float s = (fa.x + fa.y + fc.x + fc.y) * 0.125f;
            if (mw[j] != 0) s = -10000.0f;
            sc[j] = s;
        }

        float tmax = sc[0];
        #pragma unroll
        for (int j = 1; j < 32; j++) tmax = fmaxf(tmax, sc[j]);
        const float mnew = fmaxf(m, tmax);
        const float corr = __expf(m - mnew);
        float ps = 0.f;
        #pragma unroll
        for (int j = 0; j < 32; j++) {
            const float p = __expf(sc[j] - mnew);
            sc[j] = p; ps += p;
        }
        l = l * corr + ps;
        m = mnew;

        const unsigned long long cp = pack2(corr);
        #pragma unroll
        for (int i = 0; i < 32; i++) o2[i] = fmul2(o2[i], cp);

        #pragma unroll
        for (int j = 0; j < 32; j++) {
            const unsigned long long p2 = pack2(sc[j]);
            const ulonglong2* vp = (const ulonglong2*)Vs[j];
            #pragma unroll
            for (int d = 0; d < 16; d++) {
                ulonglong2 vv = vp[d];
                o2[2*d]   = ffma2(p2, vv.x, o2[2*d]);
                o2[2*d+1] = ffma2(p2, vv.y, o2[2*d+1]);
            }
        }
        __syncthreads();
    }

    const float inv = 1.0f / l;
    float2* op = (float2*)(O + ((size_t)(b * S_ + q)) * D_ + h * DK_);
    #pragma unroll
    for (int i = 0; i < 32; i++) {
        float2 f = unpack2(o2[i]);
        op[i] = make_float2(f.x * inv, f.y * inv);
    }
}

// ---------------- launcher ---------------------------------------------------
extern "C" void kernel_launch(void* const* d_in, const int* in_sizes, int n_in,
                              void* d_out, int out_size)
{
    const float* x  = (const float*)d_in[0];
    const int*   mask = (const int*)d_in[1];   // jax bool -> int32 per harness dtype map
    const float* Wq = (const float*)d_in[2];  const float* bq = (const float*)d_in[3];
    const float* Wk = (const float*)d_in[4];  const float* bk = (const float*)d_in[5];
    const float* Wv = (const float*)d_in[6];  const float* bv = (const float*)d_in[7];
    const float* Wo = (const float*)d_in[8];  const float* bo = (const float*)d_in[9];
    const float* W1 = (const float*)d_in[10]; const float* b1 = (const float*)d_in[11];
    const float* W2 = (const float*)d_in[12]; const float* b2 = (const float*)d_in[13];
    const float* ga = (const float*)d_in[14]; const float* ba = (const float*)d_in[15];
    const float* gf = (const float*)d_in[16]; const float* bf = (const float*)d_in[17];
    float* out = (float*)d_out;

    float *nx, *qb, *kb, *vb, *hb;
    cudaGetSymbolAddress((void**)&nx, g_bufA);
    cudaGetSymbolAddress((void**)&qb, g_q);
    cudaGetSymbolAddress((void**)&kb, g_k);
    cudaGetSymbolAddress((void**)&vb, g_v);
    cudaGetSymbolAddress((void**)&hb, g_h);

    // 1) LN (attn)
    ln_kernel<<<ROWS, 256>>>(x, ga, ba, nx);

    // 2) Q,K,V projections
    dim3 g1(D_ / BN, ROWS / BM);
    sgemm_nt<EPI_NONE><<<g1, 256>>>(ROWS, D_, D_, nx, Wq, bq, nullptr, qb);
    sgemm_nt<EPI_NONE><<<g1, 256>>>(ROWS, D_, D_, nx, Wk, bk, nullptr, kb);
    sgemm_nt<EPI_NONE><<<g1, 256>>>(ROWS, D_, D_, nx, Wv, bv, nullptr, vb);

    // 3) attention (ctx overwrites nx buffer)
    attn_kernel<<<dim3(S_ / 64, H_, B_), 64>>>(qb, kb, vb, mask, nx);

    // 4) O-projection + residual (x1 into qb)
    sgemm_nt<EPI_RES><<<g1, 256>>>(ROWS, D_, D_, nx, Wo, bo, x, qb);

    // 5) LN (ffn) -> nx2 into kb
    ln_kernel<<<ROWS, 256>>>(qb, gf, bf, kb);

    // 6) FFN1 + exact GELU
    dim3 g2(DFF_ / BN, ROWS / BM);
    sgemm_nt<EPI_GELU><<<g2, 256>>>(ROWS, DFF_, D_, kb, W1, b1, nullptr, hb);

    // 7) FFN2 + residual -> output
    dim3 g3(D_ / BN, ROWS / BM);
    sgemm_nt<EPI_RES><<<g3, 256>>>(ROWS, D_, DFF_, hb, W2, b2, qb, out);
}

// round 4
// speedup vs baseline: 1.7251x; 1.7251x over previous
#include <cuda_runtime.h>
#include <cstdint>

#define B_   2
#define S_   2048
#define D_   1024
#define H_   16
#define DK_  64
#define DFF_ 4096
#define ROWS (B_*S_)   // 4096

// ---------------- scratch (device globals; no allocations allowed) ----------
__device__ float g_bufA[ROWS*D_];   // nx  -> ctx
__device__ float g_q  [ROWS*D_];    // q   -> x1
__device__ float g_k  [ROWS*D_];    // k   -> nx2
__device__ float g_v  [ROWS*D_];
__device__ float g_h  [ROWS*DFF_];  // ffn hidden
// tf32-rounded weight copies
__device__ float g_wq[D_*D_], g_wk[D_*D_], g_wv[D_*D_], g_wo[D_*D_];
__device__ float g_w1[DFF_*D_], g_w2[D_*DFF_];

// ---------------- helpers ----------------------------------------------------
__device__ __forceinline__ float to_tf32(float x) {
    float r; asm("cvt.rna.tf32.f32 %0, %1;" : "=f"(r) : "f"(x)); return r;
}
__device__ __forceinline__ unsigned long long ffma2(unsigned long long a,
                                                    unsigned long long b,
                                                    unsigned long long c) {
    unsigned long long d;
    asm("fma.rn.f32x2 %0, %1, %2, %3;" : "=l"(d) : "l"(a), "l"(b), "l"(c));
    return d;
}
__device__ __forceinline__ unsigned long long fmul2(unsigned long long a,
                                                    unsigned long long b) {
    unsigned long long d;
    asm("mul.rn.f32x2 %0, %1, %2;" : "=l"(d) : "l"(a), "l"(b));
    return d;
}
__device__ __forceinline__ unsigned long long pack2(float x) {
    unsigned long long r;
    asm("mov.b64 %0, {%1, %1};" : "=l"(r) : "f"(x));
    return r;
}
__device__ __forceinline__ float2 unpack2(unsigned long long v) {
    float2 f;
    asm("mov.b64 {%0, %1}, %2;" : "=f"(f.x), "=f"(f.y) : "l"(v));
    return f;
}
__device__ __forceinline__ uint32_t smem_u32(const void* p) {
    uint32_t a;
    asm("{ .reg .u64 t; cvta.to.shared.u64 t, %1; cvt.u32.u64 %0, t; }"
        : "=r"(a) : "l"(p));
    return a;
}
__device__ __forceinline__ void cp16(uint32_t dst, const void* src) {
    asm volatile("cp.async.cg.shared.global [%0], [%1], 16;"
                 :: "r"(dst), "l"(src) : "memory");
}
__device__ __forceinline__ void cp_commit() {
    asm volatile("cp.async.commit_group;" ::: "memory");
}
// mma.sync m16n8k8 tf32: D += A*B
__device__ __forceinline__ void mma8(float* c, uint32_t a0, uint32_t a1,
                                     uint32_t a2, uint32_t a3,
                                     uint32_t b0, uint32_t b1) {
    asm volatile(
        "mma.sync.aligned.m16n8k8.row.col.f32.tf32.tf32.f32 "
        "{%0,%1,%2,%3}, {%4,%5,%6,%7}, {%8,%9}, {%0,%1,%2,%3};"
        : "+f"(c[0]), "+f"(c[1]), "+f"(c[2]), "+f"(c[3])
        : "r"(a0), "r"(a1), "r"(a2), "r"(a3), "r"(b0), "r"(b1));
}
// swizzled smem float index for a 128-row x 32-col (K-contig) tile
__device__ __forceinline__ int swz(int m, int k) {
    return m * 32 + (k ^ ((m & 7) << 2));
}

// ---------------- tf32 rounding copy ----------------------------------------
__global__ __launch_bounds__(256) void cvt_tf32_kernel(
    const float* __restrict__ in, float* __restrict__ out, int n4)
{
    int i = blockIdx.x * 256 + threadIdx.x;
    if (i < n4) {
        float4 v = ((const float4*)in)[i];
        v.x = to_tf32(v.x); v.y = to_tf32(v.y);
        v.z = to_tf32(v.z); v.w = to_tf32(v.w);
        ((float4*)out)[i] = v;
    }
}

// ---------------- LayerNorm ---------------------------------------------------
template <int RND>
__global__ __launch_bounds__(256) void ln_kernel(
    const float* __restrict__ x, const float* __restrict__ g,
    const float* __restrict__ bta, float* __restrict__ out)
{
    const int row = blockIdx.x;
    const int t   = threadIdx.x;
    const float4* xr = (const float4*)(x + (size_t)row * D_);
    float4 v = xr[t];
    float s  = v.x + v.y + v.z + v.w;
    float s2 = v.x*v.x + v.y*v.y + v.z*v.z + v.w*v.w;
    #pragma unroll
    for (int o = 16; o > 0; o >>= 1) {
        s  += __shfl_xor_sync(0xffffffffu, s,  o);
        s2 += __shfl_xor_sync(0xffffffffu, s2, o);
    }
    __shared__ float rs[8], rs2[8];
    const int w = t >> 5;
    if ((t & 31) == 0) { rs[w] = s; rs2[w] = s2; }
    __syncthreads();
    s = 0.f; s2 = 0.f;
    #pragma unroll
    for (int i = 0; i < 8; i++) { s += rs[i]; s2 += rs2[i]; }
    const float mu   = s * (1.0f / D_);
    const float var  = s2 * (1.0f / D_) - mu * mu;
    const float rstd = rsqrtf(var + 1e-5f);
    float4 gg = ((const float4*)g)[t];
    float4 bb = ((const float4*)bta)[t];
    float4 o4;
    o4.x = (v.x - mu) * rstd * gg.x + bb.x;
    o4.y = (v.y - mu) * rstd * gg.y + bb.y;
    o4.z = (v.z - mu) * rstd * gg.z + bb.z;
    o4.w = (v.w - mu) * rstd * gg.w + bb.w;
    if (RND) {
        o4.x = to_tf32(o4.x); o4.y = to_tf32(o4.y);
        o4.z = to_tf32(o4.z); o4.w = to_tf32(o4.w);
    }
    ((float4*)(out + (size_t)row * D_))[t] = o4;
}

// ---------------- TF32 tensor-core GEMM-NT (mma.sync) ------------------------
// C[M,N] = A[M,K] * Bw[N,K]^T + bias  (+residual / gelu)
// 128x128x32 CTA tile, 8 warps (2M x 4N), warp tile 64x32, cp.async dbl-buffer.
enum { EPI_NONE = 0, EPI_RES = 1, EPI_GELU = 2 };
#define GEMM_SMEM (2 * 32768)

template <int EPI>
__global__ __launch_bounds__(256) void gemm_mma(
    int M, int N, int K,
    const float* __restrict__ A, const float* __restrict__ Bw,
    const float* __restrict__ bias, const float* __restrict__ resid,
    float* __restrict__ C)
{
    extern __shared__ float sm[];   // [2][8192]: per buf: A 4096 floats, B 4096
    const int tid  = threadIdx.x;
    const int lane = tid & 31;
    const int wid  = tid >> 5;
    const int wm = wid & 1;         // 0..1 -> 64-row slice
    const int wn = wid >> 1;        // 0..3 -> 32-col slice
    const int brow = blockIdx.y * 128;
    const int bcol = blockIdx.x * 128;
    const int T = K >> 5;           // k-tiles of 32

    const uint32_t smb = smem_u32(sm);

    // per-thread cp.async slots: 4 chunks for A, 4 for B (16B each)
    int am[4], akq[4];
    #pragma unroll
    for (int p = 0; p < 4; p++) {
        const int c = tid + 256 * p;   // 0..1023
        am[p]  = c >> 3;               // row 0..127
        akq[p] = c & 7;                // 16B chunk in row
    }

    float acc[4][4][4];
    #pragma unroll
    for (int mi = 0; mi < 4; mi++)
        #pragma unroll
        for (int ni = 0; ni < 4; ni++)
            #pragma unroll
            for (int e = 0; e < 4; e++) acc[mi][ni][e] = 0.f;

    // issue loads for k-tile i into buffer bsel
    auto issue = [&](int i, int bsel) {
        const uint32_t dA = smb + bsel * 32768u;
        const uint32_t dB = dA + 16384u;
        const int kbase = i * 32;
        #pragma unroll
        for (int p = 0; p < 4; p++) {
            const int m = am[p], kq = akq[p];
            const uint32_t doff = (uint32_t)(m * 128 + (((kq ^ (m & 7)) << 4)));
            cp16(dA + doff, A  + (size_t)(brow + m) * K + kbase + kq * 4);
            cp16(dB + doff, Bw + (size_t)(bcol + m) * K + kbase + kq * 4);
        }
        cp_commit();
    };

    issue(0, 0);
    for (int i = 0; i < T; i++) {
        if (i + 1 < T) issue(i + 1, (i + 1) & 1);
        if (i + 1 < T) asm volatile("cp.async.wait_group 1;" ::: "memory");
        else           asm volatile("cp.async.wait_group 0;" ::: "memory");
        __syncthreads();

        const float* As = sm + (size_t)(i & 1) * 8192;
        const float* Bs = As + 4096;
        const int r  = lane >> 2;
        const int kk = lane & 3;

        #pragma unroll
        for (int s = 0; s < 4; s++) {
            const int k0 = s * 8;
            uint32_t af[4][4], bf[4][2];
            #pragma unroll
            for (int mi = 0; mi < 4; mi++) {
                const int m0 = wm * 64 + mi * 16 + r;
                af[mi][0] = __float_as_uint(As[swz(m0,     k0 + kk)]);
                af[mi][1] = __float_as_uint(As[swz(m0 + 8, k0 + kk)]);
                af[mi][2] = __float_as_uint(As[swz(m0,     k0 + kk + 4)]);
                af[mi][3] = __float_as_uint(As[swz(m0 + 8, k0 + kk + 4)]);
            }
            #pragma unroll
            for (int ni = 0; ni < 4; ni++) {
                const int n0 = wn * 32 + ni * 8 + r;
                bf[ni][0] = __float_as_uint(Bs[swz(n0, k0 + kk)]);
                bf[ni][1] = __float_as_uint(Bs[swz(n0, k0 + kk + 4)]);
            }
            #pragma unroll
            for (int mi = 0; mi < 4; mi++)
                #pragma unroll
                for (int ni = 0; ni < 4; ni++)
                    mma8(acc[mi][ni], af[mi][0], af[mi][1], af[mi][2], af[mi][3],
                         bf[ni][0], bf[ni][1]);
        }
        __syncthreads();
    }

    // epilogue: acc tile (mi,ni): rows r0/r0+8, cols col..col+1
    #pragma unroll
    for (int mi = 0; mi < 4; mi++) {
        #pragma unroll
        for (int ni = 0; ni < 4; ni++) {
            const int r0  = brow + wm * 64 + mi * 16 + (lane >> 2);
            const int col = bcol + wn * 32 + ni * 8 + 2 * (lane & 3);
            const float b0 = bias[col], b1 = bias[col + 1];
            float v[4] = { acc[mi][ni][0] + b0, acc[mi][ni][1] + b1,
                           acc[mi][ni][2] + b0, acc[mi][ni][3] + b1 };
            if (EPI == EPI_RES) {
                const float2 x0 = *(const float2*)&resid[(size_t)r0 * N + col];
                const float2 x1 = *(const float2*)&resid[(size_t)(r0 + 8) * N + col];
                v[0] += x0.x; v[1] += x0.y; v[2] += x1.x; v[3] += x1.y;
            }
            if (EPI == EPI_GELU) {
                #pragma unroll
                for (int e = 0; e < 4; e++) {
                    v[e] = 0.5f * v[e] * (1.0f + erff(v[e] * 0.70710678118654752f));
                    v[e] = to_tf32(v[e]);   // feeds next tf32 GEMM
                }
            }
            *(float2*)&C[(size_t)r0 * N + col]       = make_float2(v[0], v[1]);
            *(float2*)&C[(size_t)(r0 + 8) * N + col] = make_float2(v[2], v[3]);
        }
    }
}

// ---------------- flash-style attention (FFMA2), mask = int32 ----------------
__global__ __launch_bounds__(64) void attn_kernel(
    const float* __restrict__ Q, const float* __restrict__ Kg,
    const float* __restrict__ Vg, const int* __restrict__ mask,
    float* __restrict__ O)
{
    const int b = blockIdx.z, h = blockIdx.y;
    const int t = threadIdx.x;
    const int q = blockIdx.x * 64 + t;

    __shared__ __align__(16) float Ks[32][64];
    __shared__ __align__(16) float Vs[32][64];
    float4* ksp = reinterpret_cast<float4*>(&Ks[0][0]);
    float4* vsp = reinterpret_cast<float4*>(&Vs[0][0]);

    unsigned long long q2[32], o2[32];
    {
        const ulonglong2* qp =
            (const ulonglong2*)(Q + ((size_t)(b * S_ + q)) * D_ + h * DK_);
        #pragma unroll
        for (int i = 0; i < 16; i++) {
            ulonglong2 qv = qp[i];
            q2[2*i] = qv.x; q2[2*i+1] = qv.y;
        }
    }
    #pragma unroll
    for (int i = 0; i < 32; i++) o2[i] = 0ull;

    float m = -3.0e38f, l = 0.f;
    const int* mrow = mask + ((size_t)(b * S_ + q)) * S_;

    for (int kt = 0; kt < S_; kt += 32) {
        #pragma unroll
        for (int i = 0; i < 8; i++) {
            const int f4 = i * 64 + t;
            const int j = f4 >> 4, d4 = f4 & 15;
            const size_t gi = ((size_t)(b * S_ + kt + j)) * D_ + h * DK_ + d4 * 4;
            ksp[f4] = *(const float4*)&Kg[gi];
            vsp[f4] = *(const float4*)&Vg[gi];
        }
        __syncthreads();

        int mw[32];
        #pragma unroll
        for (int i = 0; i < 8; i++)
            *(int4*)&mw[i * 4] = *(const int4*)(mrow + kt + i * 4);

        float sc[32];
        #pragma unroll
        for (int j = 0; j < 32; j++) {
            const ulonglong2* kp = (const ulonglong2*)Ks[j];
            unsigned long long a2 = 0ull, c2 = 0ull;
            #pragma unroll
            for (int d = 0; d < 16; d++) {
                ulonglong2 kv = kp[d];
                a2 = ffma2(q2[2*d],   kv.x, a2);
                c2 = ffma2(q2[2*d+1], kv.y, c2);
            }
            float2 fa = unpack2(a2), fc = unpack2(c2);
            float s = (fa.x + fa.y + fc.x + fc.y) * 0.125f;
            if (mw[j] != 0) s = -10000.0f;
            sc[j] = s;
        }

        float tmax = sc[0];
        #pragma unroll
        for (int j = 1; j < 32; j++) tmax = fmaxf(tmax, sc[j]);
        const float mnew = fmaxf(m, tmax);
        const float corr = __expf(m - mnew);
        float ps = 0.f;
        #pragma unroll
        for (int j = 0; j < 32; j++) {
            const float p = __expf(sc[j] - mnew);
            sc[j] = p; ps += p;
        }
        l = l * corr + ps;
        m = mnew;

        const unsigned long long cp = pack2(corr);
        #pragma unroll
        for (int i = 0; i < 32; i++) o2[i] = fmul2(o2[i], cp);

        #pragma unroll
        for (int j = 0; j < 32; j++) {
            const unsigned long long p2 = pack2(sc[j]);
            const ulonglong2* vp = (const ulonglong2*)Vs[j];
            #pragma unroll
            for (int d = 0; d < 16; d++) {
                ulonglong2 vv = vp[d];
                o2[2*d]   = ffma2(p2, vv.x, o2[2*d]);
                o2[2*d+1] = ffma2(p2, vv.y, o2[2*d+1]);
            }
        }
        __syncthreads();
    }

    const float inv = 1.0f / l;
    float2* op = (float2*)(O + ((size_t)(b * S_ + q)) * D_ + h * DK_);
    #pragma unroll
    for (int i = 0; i < 32; i++) {
        float2 f = unpack2(o2[i]);
        op[i] = make_float2(to_tf32(f.x * inv), to_tf32(f.y * inv)); // feeds tf32 GEMM
    }
}

// ---------------- launcher ----------------------------------------------------
extern "C" void kernel_launch(void* const* d_in, const int* in_sizes, int n_in,
                              void* d_out, int out_size)
{
    const float* x  = (const float*)d_in[0];
    const int*   mask = (const int*)d_in[1];
    const float* Wq = (const float*)d_in[2];  const float* bq = (const float*)d_in[3];
    const float* Wk = (const float*)d_in[4];  const float* bk = (const float*)d_in[5];
    const float* Wv = (const float*)d_in[6];  const float* bv = (const float*)d_in[7];
    const float* Wo = (const float*)d_in[8];  const float* bo = (const float*)d_in[9];
    const float* W1 = (const float*)d_in[10]; const float* b1 = (const float*)d_in[11];
    const float* W2 = (const float*)d_in[12]; const float* b2 = (const float*)d_in[13];
    const float* ga = (const float*)d_in[14]; const float* ba = (const float*)d_in[15];
    const float* gf = (const float*)d_in[16]; const float* bf = (const float*)d_in[17];
    float* out = (float*)d_out;

    float *nx, *qb, *kb, *vb, *hb;
    float *wq, *wk, *wv, *wo, *w1, *w2;
    cudaGetSymbolAddress((void**)&nx, g_bufA);
    cudaGetSymbolAddress((void**)&qb, g_q);
    cudaGetSymbolAddress((void**)&kb, g_k);
    cudaGetSymbolAddress((void**)&vb, g_v);
    cudaGetSymbolAddress((void**)&hb, g_h);
    cudaGetSymbolAddress((void**)&wq, g_wq);
    cudaGetSymbolAddress((void**)&wk, g_wk);
    cudaGetSymbolAddress((void**)&wv, g_wv);
    cudaGetSymbolAddress((void**)&wo, g_wo);
    cudaGetSymbolAddress((void**)&w1, g_w1);
    cudaGetSymbolAddress((void**)&w2, g_w2);

    cudaFuncSetAttribute(gemm_mma<EPI_NONE>,
                         cudaFuncAttributeMaxDynamicSharedMemorySize, GEMM_SMEM);
    cudaFuncSetAttribute(gemm_mma<EPI_RES>,
                         cudaFuncAttributeMaxDynamicSharedMemorySize, GEMM_SMEM);
    cudaFuncSetAttribute(gemm_mma<EPI_GELU>,
                         cudaFuncAttributeMaxDynamicSharedMemorySize, GEMM_SMEM);

    // 0) round weights to tf32 once per launch
    const int ndd4 = D_ * D_ / 4, ndf4 = DFF_ * D_ / 4;
    cvt_tf32_kernel<<<(ndd4 + 255) / 256, 256>>>(Wq, wq, ndd4);
    cvt_tf32_kernel<<<(ndd4 + 255) / 256, 256>>>(Wk, wk, ndd4);
    cvt_tf32_kernel<<<(ndd4 + 255) / 256, 256>>>(Wv, wv, ndd4);
    cvt_tf32_kernel<<<(ndd4 + 255) / 256, 256>>>(Wo, wo, ndd4);
    cvt_tf32_kernel<<<(ndf4 + 255) / 256, 256>>>(W1, w1, ndf4);
    cvt_tf32_kernel<<<(ndf4 + 255) / 256, 256>>>(W2, w2, ndf4);

    // 1) LN (attn), tf32-rounded
    ln_kernel<1><<<ROWS, 256>>>(x, ga, ba, nx);

    // 2) Q,K,V projections (tensor cores)
    dim3 g1(D_ / 128, ROWS / 128);
    gemm_mma<EPI_NONE><<<g1, 256, GEMM_SMEM>>>(ROWS, D_, D_, nx, wq, bq, nullptr, qb);
    gemm_mma<EPI_NONE><<<g1, 256, GEMM_SMEM>>>(ROWS, D_, D_, nx, wk, bk, nullptr, kb);
    gemm_mma<EPI_NONE><<<g1, 256, GEMM_SMEM>>>(ROWS, D_, D_, nx, wv, bv, nullptr, vb);

    // 3) attention (ctx -> nx, tf32-rounded)
    attn_kernel<<<dim3(S_ / 64, H_, B_), 64>>>(qb, kb, vb, mask, nx);

    // 4) O-projection + residual -> x1 (qb)
    gemm_mma<EPI_RES><<<g1, 256, GEMM_SMEM>>>(ROWS, D_, D_, nx, wo, bo, x, qb);

    // 5) LN (ffn) -> nx2 (kb), tf32-rounded
    ln_kernel<1><<<ROWS, 256>>>(qb, gf, bf, kb);

    // 6) FFN1 + exact GELU (tf32-rounded)
    dim3 g2(DFF_ / 128, ROWS / 128);
    gemm_mma<EPI_GELU><<<g2, 256, GEMM_SMEM>>>(ROWS, DFF_, D_, kb, w1, b1, nullptr, hb);

    // 7) FFN2 + residual -> output
    dim3 g3(D_ / 128, ROWS / 128);
    gemm_mma<EPI_RES><<<g3, 256, GEMM_SMEM>>>(ROWS, D_, DFF_, hb, w2, b2, qb, out);
}

// round 5
// speedup vs baseline: 2.9436x; 1.7063x over previous
#include <cuda_runtime.h>
#include <cuda_bf16.h>
#include <cstdint>

#define B_   2
#define S_   2048
#define D_   1024
#define H_   16
#define DK_  64
#define DFF_ 4096
#define ROWS (B_*S_)     // 4096
#define QKV_S (3*D_)     // 3072

// ---------------- scratch (device globals; no allocations allowed) ----------
__device__ float g_bufA[ROWS*D_];      // nx -> ctx
__device__ float g_x1 [ROWS*D_];       // x after attn residual
__device__ float g_qkv[ROWS*QKV_S];    // packed q|k|v ; later reused as nx2
__device__ float g_h  [ROWS*DFF_];     // ffn hidden
// tf32-rounded weights
__device__ float g_wqkv[3*D_*D_];
__device__ float g_bqkv[3*D_];
__device__ float g_wo[D_*D_];
__device__ float g_w1[DFF_*D_], g_w2[D_*DFF_];

// ---------------- helpers ----------------------------------------------------
__device__ __forceinline__ float to_tf32(float x) {
    float r; asm("cvt.rna.tf32.f32 %0, %1;" : "=f"(r) : "f"(x)); return r;
}
__device__ __forceinline__ uint32_t smem_u32(const void* p) {
    uint32_t a;
    asm("{ .reg .u64 t; cvta.to.shared.u64 t, %1; cvt.u32.u64 %0, t; }"
        : "=r"(a) : "l"(p));
    return a;
}
__device__ __forceinline__ void cp16(uint32_t dst, const void* src) {
    asm volatile("cp.async.cg.shared.global [%0], [%1], 16;"
                 :: "r"(dst), "l"(src) : "memory");
}
__device__ __forceinline__ void cp_commit() {
    asm volatile("cp.async.commit_group;" ::: "memory");
}
// m16n8k8 tf32: C += A*B
__device__ __forceinline__ void mma8(float* c, uint32_t a0, uint32_t a1,
                                     uint32_t a2, uint32_t a3,
                                     uint32_t b0, uint32_t b1) {
    asm volatile(
        "mma.sync.aligned.m16n8k8.row.col.f32.tf32.tf32.f32 "
        "{%0,%1,%2,%3}, {%4,%5,%6,%7}, {%8,%9}, {%0,%1,%2,%3};"
        : "+f"(c[0]), "+f"(c[1]), "+f"(c[2]), "+f"(c[3])
        : "r"(a0), "r"(a1), "r"(a2), "r"(a3), "r"(b0), "r"(b1));
}
// m16n8k16 bf16: C += A*B
__device__ __forceinline__ void mma16bf(float* c, const uint32_t* a,
                                        uint32_t b0, uint32_t b1) {
    asm volatile(
        "mma.sync.aligned.m16n8k16.row.col.f32.bf16.bf16.f32 "
        "{%0,%1,%2,%3}, {%4,%5,%6,%7}, {%8,%9}, {%0,%1,%2,%3};"
        : "+f"(c[0]), "+f"(c[1]), "+f"(c[2]), "+f"(c[3])
        : "r"(a[0]), "r"(a[1]), "r"(a[2]), "r"(a[3]), "r"(b0), "r"(b1));
}
// pack two f32 -> bf16x2 (lo = first arg)
__device__ __forceinline__ uint32_t bf16pk(float lo, float hi) {
    uint32_t r;
    asm("cvt.rn.bf16x2.f32 %0, %1, %2;" : "=r"(r) : "f"(hi), "f"(lo));
    return r;
}
// swizzled smem float index for a 128-row x 32-col (K-contig) GEMM tile
__device__ __forceinline__ int swz(int m, int k) {
    return m * 32 + (k ^ ((m & 7) << 2));
}

// ---------------- tf32 rounding copy ----------------------------------------
__global__ __launch_bounds__(256) void cvt_tf32_kernel(
    const float* __restrict__ in, float* __restrict__ out, int n4)
{
    int i = blockIdx.x * 256 + threadIdx.x;
    if (i < n4) {
        float4 v = ((const float4*)in)[i];
        v.x = to_tf32(v.x); v.y = to_tf32(v.y);
        v.z = to_tf32(v.z); v.w = to_tf32(v.w);
        ((float4*)out)[i] = v;
    }
}
__global__ __launch_bounds__(256) void pack_bias_kernel(
    const float* __restrict__ a, const float* __restrict__ b,
    const float* __restrict__ c, float* __restrict__ o)
{
    int i = blockIdx.x * 256 + threadIdx.x;
    if (i < D_) { o[i] = a[i]; o[D_ + i] = b[i]; o[2*D_ + i] = c[i]; }
}

// ---------------- LayerNorm ---------------------------------------------------
template <int RND>
__global__ __launch_bounds__(256) void ln_kernel(
    const float* __restrict__ x, const float* __restrict__ g,
    const float* __restrict__ bta, float* __restrict__ out)
{
    const int row = blockIdx.x;
    const int t   = threadIdx.x;
    const float4* xr = (const float4*)(x + (size_t)row * D_);
    float4 v = xr[t];
    float s  = v.x + v.y + v.z + v.w;
    float s2 = v.x*v.x + v.y*v.y + v.z*v.z + v.w*v.w;
    #pragma unroll
    for (int o = 16; o > 0; o >>= 1) {
        s  += __shfl_xor_sync(0xffffffffu, s,  o);
        s2 += __shfl_xor_sync(0xffffffffu, s2, o);
    }
    __shared__ float rs[8], rs2[8];
    const int w = t >> 5;
    if ((t & 31) == 0) { rs[w] = s; rs2[w] = s2; }
    __syncthreads();
    s = 0.f; s2 = 0.f;
    #pragma unroll
    for (int i = 0; i < 8; i++) { s += rs[i]; s2 += rs2[i]; }
    const float mu   = s * (1.0f / D_);
    const float var  = s2 * (1.0f / D_) - mu * mu;
    const float rstd = rsqrtf(var + 1e-5f);
    float4 gg = ((const float4*)g)[t];
    float4 bb = ((const float4*)bta)[t];
    float4 o4;
    o4.x = (v.x - mu) * rstd * gg.x + bb.x;
    o4.y = (v.y - mu) * rstd * gg.y + bb.y;
    o4.z = (v.z - mu) * rstd * gg.z + bb.z;
    o4.w = (v.w - mu) * rstd * gg.w + bb.w;
    if (RND) {
        o4.x = to_tf32(o4.x); o4.y = to_tf32(o4.y);
        o4.z = to_tf32(o4.z); o4.w = to_tf32(o4.w);
    }
    ((float4*)(out + (size_t)row * D_))[t] = o4;
}

// ---------------- TF32 tensor-core GEMM-NT (mma.sync) ------------------------
enum { EPI_NONE = 0, EPI_RES = 1, EPI_GELU = 2 };
#define GEMM_SMEM (2 * 32768)

template <int EPI>
__global__ __launch_bounds__(256) void gemm_mma(
    int M, int N, int K,
    const float* __restrict__ A, const float* __restrict__ Bw,
    const float* __restrict__ bias, const float* __restrict__ resid,
    float* __restrict__ C)
{
    extern __shared__ float sm[];   // [2][8192]: per buf: A 4096 floats, B 4096
    const int tid  = threadIdx.x;
    const int lane = tid & 31;
    const int wid  = tid >> 5;
    const int wm = wid & 1;
    const int wn = wid >> 1;
    const int brow = blockIdx.y * 128;
    const int bcol = blockIdx.x * 128;
    const int T = K >> 5;

    const uint32_t smb = smem_u32(sm);

    int am[4], akq[4];
    #pragma unroll
    for (int p = 0; p < 4; p++) {
        const int c = tid + 256 * p;
        am[p]  = c >> 3;
        akq[p] = c & 7;
    }

    float acc[4][4][4];
    #pragma unroll
    for (int mi = 0; mi < 4; mi++)
        #pragma unroll
        for (int ni = 0; ni < 4; ni++)
            #pragma unroll
            for (int e = 0; e < 4; e++) acc[mi][ni][e] = 0.f;

    auto issue = [&](int i, int bsel) {
        const uint32_t dA = smb + bsel * 32768u;
        const uint32_t dB = dA + 16384u;
        const int kbase = i * 32;
        #pragma unroll
        for (int p = 0; p < 4; p++) {
            const int m = am[p], kq = akq[p];
            const uint32_t doff = (uint32_t)(m * 128 + (((kq ^ (m & 7)) << 4)));
            cp16(dA + doff, A  + (size_t)(brow + m) * K + kbase + kq * 4);
            cp16(dB + doff, Bw + (size_t)(bcol + m) * K + kbase + kq * 4);
        }
        cp_commit();
    };

    issue(0, 0);
    for (int i = 0; i < T; i++) {
        if (i + 1 < T) issue(i + 1, (i + 1) & 1);
        if (i + 1 < T) asm volatile("cp.async.wait_group 1;" ::: "memory");
        else           asm volatile("cp.async.wait_group 0;" ::: "memory");
        __syncthreads();

        const float* As = sm + (size_t)(i & 1) * 8192;
        const float* Bs = As + 4096;
        const int r  = lane >> 2;
        const int kk = lane & 3;

        #pragma unroll
        for (int s = 0; s < 4; s++) {
            const int k0 = s * 8;
            uint32_t af[4][4], bf[4][2];
            #pragma unroll
            for (int mi = 0; mi < 4; mi++) {
                const int m0 = wm * 64 + mi * 16 + r;
                af[mi][0] = __float_as_uint(As[swz(m0,     k0 + kk)]);
                af[mi][1] = __float_as_uint(As[swz(m0 + 8, k0 + kk)]);
                af[mi][2] = __float_as_uint(As[swz(m0,     k0 + kk + 4)]);
                af[mi][3] = __float_as_uint(As[swz(m0 + 8, k0 + kk + 4)]);
            }
            #pragma unroll
            for (int ni = 0; ni < 4; ni++) {
                const int n0 = wn * 32 + ni * 8 + r;
                bf[ni][0] = __float_as_uint(Bs[swz(n0, k0 + kk)]);
                bf[ni][1] = __float_as_uint(Bs[swz(n0, k0 + kk + 4)]);
            }
            #pragma unroll
            for (int mi = 0; mi < 4; mi++)
                #pragma unroll
                for (int ni = 0; ni < 4; ni++)
                    mma8(acc[mi][ni], af[mi][0], af[mi][1], af[mi][2], af[mi][3],
                         bf[ni][0], bf[ni][1]);
        }
        __syncthreads();
    }

    #pragma unroll
    for (int mi = 0; mi < 4; mi++) {
        #pragma unroll
        for (int ni = 0; ni < 4; ni++) {
            const int r0  = brow + wm * 64 + mi * 16 + (lane >> 2);
            const int col = bcol + wn * 32 + ni * 8 + 2 * (lane & 3);
            const float b0 = bias[col], b1 = bias[col + 1];
            float v[4] = { acc[mi][ni][0] + b0, acc[mi][ni][1] + b1,
                           acc[mi][ni][2] + b0, acc[mi][ni][3] + b1 };
            if (EPI == EPI_RES) {
                const float2 x0 = *(const float2*)&resid[(size_t)r0 * N + col];
                const float2 x1 = *(const float2*)&resid[(size_t)(r0 + 8) * N + col];
                v[0] += x0.x; v[1] += x0.y; v[2] += x1.x; v[3] += x1.y;
            }
            if (EPI == EPI_GELU) {
                #pragma unroll
                for (int e = 0; e < 4; e++) {
                    v[e] = 0.5f * v[e] * (1.0f + erff(v[e] * 0.70710678118654752f));
                    v[e] = to_tf32(v[e]);
                }
            }
            *(float2*)&C[(size_t)r0 * N + col]       = make_float2(v[0], v[1]);
            *(float2*)&C[(size_t)(r0 + 8) * N + col] = make_float2(v[2], v[3]);
        }
    }
}

// ---------------- tensor-core flash attention --------------------------------
// grid (S/128, H, B), 256 threads (8 warps), warp = 16 query rows.
// QKᵀ: m16n8k8 tf32 ; P·V: m16n8k16 bf16 using C-layout == A-layout identity.
__global__ __launch_bounds__(256) void attn_mma(
    const float* __restrict__ QKV, const int* __restrict__ mask,
    float* __restrict__ O)
{
    __shared__ __align__(16) float Ks[64][68];          // [key][dk] fp32
    __shared__ __align__(16) __nv_bfloat16 Vs[64][72];  // [dk][key] bf16

    const int b = blockIdx.z, h = blockIdx.y;
    const int tid = threadIdx.x, lane = tid & 31, wid = tid >> 5;
    const int gp = lane >> 2, tg = lane & 3;
    const int qrow0 = blockIdx.x * 128 + wid * 16 + gp;   // within sequence

    const float* Qb = QKV + (size_t)(b * S_) * QKV_S + h * DK_;
    const float* Kb = Qb + D_;
    const float* Vb = Qb + 2 * D_;

    // Q fragments (x 1/8 scale folded in; exact in tf32)
    uint32_t qf[8][4];
    {
        const float* q0p = Qb + (size_t)qrow0 * QKV_S;
        const float* q1p = q0p + (size_t)8 * QKV_S;
        #pragma unroll
        for (int s = 0; s < 8; s++) {
            qf[s][0] = __float_as_uint(q0p[tg + 8*s]     * 0.125f);
            qf[s][1] = __float_as_uint(q1p[tg + 8*s]     * 0.125f);
            qf[s][2] = __float_as_uint(q0p[tg + 8*s + 4] * 0.125f);
            qf[s][3] = __float_as_uint(q1p[tg + 8*s + 4] * 0.125f);
        }
    }

    float oa[8][4];
    #pragma unroll
    for (int j = 0; j < 8; j++)
        #pragma unroll
        for (int e = 0; e < 4; e++) oa[j][e] = 0.f;
    float m0c = -1e30f, m1c = -1e30f, l0 = 0.f, l1 = 0.f;

    const int* mr0 = mask + ((size_t)(b * S_ + qrow0)) * S_;
    const int* mr1 = mr0 + (size_t)8 * S_;

    for (int kt = 0; kt < S_; kt += 64) {
        // stage K (fp32) and V (bf16, transposed) tiles
        #pragma unroll
        for (int p = 0; p < 4; p++) {
            const int c = tid + 256 * p;
            const int key = c >> 4, d4 = (c & 15) * 4;
            const size_t gk = (size_t)(kt + key) * QKV_S + d4;
            float4 k4 = *(const float4*)&Kb[gk];
            *(float4*)&Ks[key][d4] = k4;
            float4 v4 = *(const float4*)&Vb[gk];
            Vs[d4 + 0][key] = __float2bfloat16(v4.x);
            Vs[d4 + 1][key] = __float2bfloat16(v4.y);
            Vs[d4 + 2][key] = __float2bfloat16(v4.z);
            Vs[d4 + 3][key] = __float2bfloat16(v4.w);
        }
        __syncthreads();

        // S = (Q/8)·Kᵀ   (8 n-tiles of 8 keys, 8 k-steps of dk)
        float sc[8][4];
        #pragma unroll
        for (int j = 0; j < 8; j++)
            #pragma unroll
            for (int e = 0; e < 4; e++) sc[j][e] = 0.f;
        #pragma unroll
        for (int s = 0; s < 8; s++) {
            #pragma unroll
            for (int j = 0; j < 8; j++) {
                const uint32_t kb0 = __float_as_uint(Ks[8*j + gp][tg + 8*s]);
                const uint32_t kb1 = __float_as_uint(Ks[8*j + gp][tg + 8*s + 4]);
                mma8(sc[j], qf[s][0], qf[s][1], qf[s][2], qf[s][3], kb0, kb1);
            }
        }

        // mask (exact -10000.0 semantics)
        #pragma unroll
        for (int j = 0; j < 8; j++) {
            const int2 mm0 = *(const int2*)&mr0[kt + 8*j + 2*tg];
            const int2 mm1 = *(const int2*)&mr1[kt + 8*j + 2*tg];
            if (mm0.x) sc[j][0] = -10000.0f;
            if (mm0.y) sc[j][1] = -10000.0f;
            if (mm1.x) sc[j][2] = -10000.0f;
            if (mm1.y) sc[j][3] = -10000.0f;
        }

        // online softmax (rows r and r+8 tracked separately)
        float t0 = -1e30f, t1 = -1e30f;
        #pragma unroll
        for (int j = 0; j < 8; j++) {
            t0 = fmaxf(t0, fmaxf(sc[j][0], sc[j][1]));
            t1 = fmaxf(t1, fmaxf(sc[j][2], sc[j][3]));
        }
        t0 = fmaxf(t0, __shfl_xor_sync(0xffffffffu, t0, 1));
        t0 = fmaxf(t0, __shfl_xor_sync(0xffffffffu, t0, 2));
        t1 = fmaxf(t1, __shfl_xor_sync(0xffffffffu, t1, 1));
        t1 = fmaxf(t1, __shfl_xor_sync(0xffffffffu, t1, 2));
        const float mn0 = fmaxf(m0c, t0), mn1 = fmaxf(m1c, t1);
        const float cr0 = __expf(m0c - mn0), cr1 = __expf(m1c - mn1);
        float ps0 = 0.f, ps1 = 0.f;
        #pragma unroll
        for (int j = 0; j < 8; j++) {
            sc[j][0] = __expf(sc[j][0] - mn0); ps0 += sc[j][0];
            sc[j][1] = __expf(sc[j][1] - mn0); ps0 += sc[j][1];
            sc[j][2] = __expf(sc[j][2] - mn1); ps1 += sc[j][2];
            sc[j][3] = __expf(sc[j][3] - mn1); ps1 += sc[j][3];
        }
        ps0 += __shfl_xor_sync(0xffffffffu, ps0, 1);
        ps0 += __shfl_xor_sync(0xffffffffu, ps0, 2);
        ps1 += __shfl_xor_sync(0xffffffffu, ps1, 1);
        ps1 += __shfl_xor_sync(0xffffffffu, ps1, 2);
        l0 = l0 * cr0 + ps0; m0c = mn0;
        l1 = l1 * cr1 + ps1; m1c = mn1;
        #pragma unroll
        for (int j = 0; j < 8; j++) {
            oa[j][0] *= cr0; oa[j][1] *= cr0;
            oa[j][2] *= cr1; oa[j][3] *= cr1;
        }

        // P (C layout) -> bf16 A fragments, zero-cost layout identity
        uint32_t pa[4][4];
        #pragma unroll
        for (int t = 0; t < 4; t++) {
            pa[t][0] = bf16pk(sc[2*t][0],     sc[2*t][1]);
            pa[t][1] = bf16pk(sc[2*t][2],     sc[2*t][3]);
            pa[t][2] = bf16pk(sc[2*t + 1][0], sc[2*t + 1][1]);
            pa[t][3] = bf16pk(sc[2*t + 1][2], sc[2*t + 1][3]);
        }

        // O += P·V   (8 dk n-tiles, 4 key k16-tiles)
        #pragma unroll
        for (int j = 0; j < 8; j++) {
            #pragma unroll
            for (int t = 0; t < 4; t++) {
                const uint32_t vb0 =
                    *(const uint32_t*)&Vs[8*j + gp][16*t + 2*tg];
                const uint32_t vb1 =
                    *(const uint32_t*)&Vs[8*j + gp][16*t + 8 + 2*tg];
                mma16bf(oa[j], pa[t], vb0, vb1);
            }
        }
        __syncthreads();
    }

    const float inv0 = 1.0f / l0, inv1 = 1.0f / l1;
    float* o0 = O + ((size_t)(b * S_ + qrow0)) * D_ + h * DK_;
    float* o1 = o0 + (size_t)8 * D_;
    #pragma unroll
    for (int j = 0; j < 8; j++) {
        *(float2*)&o0[8*j + 2*tg] =
            make_float2(to_tf32(oa[j][0] * inv0), to_tf32(oa[j][1] * inv0));
        *(float2*)&o1[8*j + 2*tg] =
            make_float2(to_tf32(oa[j][2] * inv1), to_tf32(oa[j][3] * inv1));
    }
}

// ---------------- launcher ----------------------------------------------------
extern "C" void kernel_launch(void* const* d_in, const int* in_sizes, int n_in,
                              void* d_out, int out_size)
{
    const float* x  = (const float*)d_in[0];
    const int*   mask = (const int*)d_in[1];
    const float* Wq = (const float*)d_in[2];  const float* bq = (const float*)d_in[3];
    const float* Wk = (const float*)d_in[4];  const float* bk = (const float*)d_in[5];
    const float* Wv = (const float*)d_in[6];  const float* bv = (const float*)d_in[7];
    const float* Wo = (const float*)d_in[8];  const float* bo = (const float*)d_in[9];
    const float* W1 = (const float*)d_in[10]; const float* b1 = (const float*)d_in[11];
    const float* W2 = (const float*)d_in[12]; const float* b2 = (const float*)d_in[13];
    const float* ga = (const float*)d_in[14]; const float* ba = (const float*)d_in[15];
    const float* gf = (const float*)d_in[16]; const float* bf = (const float*)d_in[17];
    float* out = (float*)d_out;

    float *nx, *x1, *qkv, *hb, *wqkv, *bqkv, *wo, *w1, *w2;
    cudaGetSymbolAddress((void**)&nx,   g_bufA);
    cudaGetSymbolAddress((void**)&x1,   g_x1);
    cudaGetSymbolAddress((void**)&qkv,  g_qkv);
    cudaGetSymbolAddress((void**)&hb,   g_h);
    cudaGetSymbolAddress((void**)&wqkv, g_wqkv);
    cudaGetSymbolAddress((void**)&bqkv, g_bqkv);
    cudaGetSymbolAddress((void**)&wo,   g_wo);
    cudaGetSymbolAddress((void**)&w1,   g_w1);
    cudaGetSymbolAddress((void**)&w2,   g_w2);

    cudaFuncSetAttribute(gemm_mma<EPI_NONE>,
                         cudaFuncAttributeMaxDynamicSharedMemorySize, GEMM_SMEM);
    cudaFuncSetAttribute(gemm_mma<EPI_RES>,
                         cudaFuncAttributeMaxDynamicSharedMemorySize, GEMM_SMEM);
    cudaFuncSetAttribute(gemm_mma<EPI_GELU>,
                         cudaFuncAttributeMaxDynamicSharedMemorySize, GEMM_SMEM);

    // 0) tf32-round weights; pack QKV weights + biases
    const int ndd4 = D_ * D_ / 4, ndf4 = DFF_ * D_ / 4;
    cvt_tf32_kernel<<<(ndd4 + 255) / 256, 256>>>(Wq, wqkv,             ndd4);
    cvt_tf32_kernel<<<(ndd4 + 255) / 256, 256>>>(Wk, wqkv + D_*D_,     ndd4);
    cvt_tf32_kernel<<<(ndd4 + 255) / 256, 256>>>(Wv, wqkv + 2*D_*D_,   ndd4);
    cvt_tf32_kernel<<<(ndd4 + 255) / 256, 256>>>(Wo, wo, ndd4);
    cvt_tf32_kernel<<<(ndf4 + 255) / 256, 256>>>(W1, w1, ndf4);
    cvt_tf32_kernel<<<(ndf4 + 255) / 256, 256>>>(W2, w2, ndf4);
    pack_bias_kernel<<<(D_ + 255) / 256, 256>>>(bq, bk, bv, bqkv);

    // 1) LN (attn), tf32-rounded
    ln_kernel<1><<<ROWS, 256>>>(x, ga, ba, nx);

    // 2) fused QKV projection
    dim3 gqkv(QKV_S / 128, ROWS / 128);
    gemm_mma<EPI_NONE><<<gqkv, 256, GEMM_SMEM>>>(ROWS, QKV_S, D_, nx, wqkv, bqkv,
                                                 nullptr, qkv);

    // 3) tensor-core flash attention (ctx -> nx, tf32-rounded)
    attn_mma<<<dim3(S_ / 128, H_, B_), 256>>>(qkv, mask, nx);

    // 4) O-projection + residual -> x1
    dim3 g1(D_ / 128, ROWS / 128);
    gemm_mma<EPI_RES><<<g1, 256, GEMM_SMEM>>>(ROWS, D_, D_, nx, wo, bo, x, x1);

    // 5) LN (ffn) -> nx2 (reuse qkv buffer), tf32-rounded
    ln_kernel<1><<<ROWS, 256>>>(x1, gf, bf, qkv);

    // 6) FFN1 + exact GELU (tf32-rounded)
    dim3 g2(DFF_ / 128, ROWS / 128);
    gemm_mma<EPI_GELU><<<g2, 256, GEMM_SMEM>>>(ROWS, DFF_, D_, qkv, w1, b1,
                                               nullptr, hb);

    // 7) FFN2 + residual -> output
    gemm_mma<EPI_RES><<<g1, 256, GEMM_SMEM>>>(ROWS, D_, DFF_, hb, w2, b2, x1, out);
}

// round 6
// speedup vs baseline: 3.5491x; 1.2057x over previous
#include <cuda_runtime.h>
#include <cuda_bf16.h>
#include <cstdint>

#define B_   2
#define S_   2048
#define D_   1024
#define H_   16
#define DK_  64
#define DFF_ 4096
#define ROWS (B_*S_)     // 4096
#define QKV_S (3*D_)     // 3072

// ---------------- scratch (device globals; no allocations allowed) ----------
__device__ float g_bufA[ROWS*D_];      // nx -> ctx
__device__ float g_x1 [ROWS*D_];       // x after attn residual
__device__ float g_qkv[ROWS*QKV_S];    // packed q|k|v ; later reused as nx2
__device__ float g_h  [ROWS*DFF_];     // ffn hidden
// tf32-rounded weights
__device__ float g_wqkv[3*D_*D_];
__device__ float g_bqkv[3*D_];
__device__ float g_wo[D_*D_];
__device__ float g_w1[DFF_*D_], g_w2[D_*DFF_];

// ---------------- helpers ----------------------------------------------------
__device__ __forceinline__ float to_tf32(float x) {
    float r; asm("cvt.rna.tf32.f32 %0, %1;" : "=f"(r) : "f"(x)); return r;
}
__device__ __forceinline__ uint32_t smem_u32(const void* p) {
    uint32_t a;
    asm("{ .reg .u64 t; cvta.to.shared.u64 t, %1; cvt.u32.u64 %0, t; }"
        : "=r"(a) : "l"(p));
    return a;
}
__device__ __forceinline__ void cp16(uint32_t dst, const void* src) {
    asm volatile("cp.async.cg.shared.global [%0], [%1], 16;"
                 :: "r"(dst), "l"(src) : "memory");
}
__device__ __forceinline__ void cp_commit() {
    asm volatile("cp.async.commit_group;" ::: "memory");
}
// ldmatrix x4: four 8x8 b16 tiles (== four 8x4 f32 tiles, tf32 fragment layout)
__device__ __forceinline__ void ldsm4(uint32_t* r, uint32_t addr) {
    asm volatile("ldmatrix.sync.aligned.m8n8.x4.shared.b16 {%0,%1,%2,%3}, [%4];"
                 : "=r"(r[0]), "=r"(r[1]), "=r"(r[2]), "=r"(r[3]) : "r"(addr));
}
// m16n8k8 tf32: C += A*B
__device__ __forceinline__ void mma8(float* c, uint32_t a0, uint32_t a1,
                                     uint32_t a2, uint32_t a3,
                                     uint32_t b0, uint32_t b1) {
    asm volatile(
        "mma.sync.aligned.m16n8k8.row.col.f32.tf32.tf32.f32 "
        "{%0,%1,%2,%3}, {%4,%5,%6,%7}, {%8,%9}, {%0,%1,%2,%3};"
        : "+f"(c[0]), "+f"(c[1]), "+f"(c[2]), "+f"(c[3])
        : "r"(a0), "r"(a1), "r"(a2), "r"(a3), "r"(b0), "r"(b1));
}
// m16n8k16 bf16: C += A*B
__device__ __forceinline__ void mma16bf(float* c, const uint32_t* a,
                                        uint32_t b0, uint32_t b1) {
    asm volatile(
        "mma.sync.aligned.m16n8k16.row.col.f32.bf16.bf16.f32 "
        "{%0,%1,%2,%3}, {%4,%5,%6,%7}, {%8,%9}, {%0,%1,%2,%3};"
        : "+f"(c[0]), "+f"(c[1]), "+f"(c[2]), "+f"(c[3])
        : "r"(a[0]), "r"(a[1]), "r"(a[2]), "r"(a[3]), "r"(b0), "r"(b1));
}
__device__ __forceinline__ uint32_t bf16pk(float lo, float hi) {
    uint32_t r;
    asm("cvt.rn.bf16x2.f32 %0, %1, %2;" : "=r"(r) : "f"(hi), "f"(lo));
    return r;
}

// ---------------- tf32 rounding copy ----------------------------------------
__global__ __launch_bounds__(256) void cvt_tf32_kernel(
    const float* __restrict__ in, float* __restrict__ out, int n4)
{
    int i = blockIdx.x * 256 + threadIdx.x;
    if (i < n4) {
        float4 v = ((const float4*)in)[i];
        v.x = to_tf32(v.x); v.y = to_tf32(v.y);
        v.z = to_tf32(v.z); v.w = to_tf32(v.w);
        ((float4*)out)[i] = v;
    }
}
__global__ __launch_bounds__(256) void pack_bias_kernel(
    const float* __restrict__ a, const float* __restrict__ b,
    const float* __restrict__ c, float* __restrict__ o)
{
    int i = blockIdx.x * 256 + threadIdx.x;
    if (i < D_) { o[i] = a[i]; o[D_ + i] = b[i]; o[2*D_ + i] = c[i]; }
}

// ---------------- LayerNorm ---------------------------------------------------
template <int RND>
__global__ __launch_bounds__(256) void ln_kernel(
    const float* __restrict__ x, const float* __restrict__ g,
    const float* __restrict__ bta, float* __restrict__ out)
{
    const int row = blockIdx.x;
    const int t   = threadIdx.x;
    const float4* xr = (const float4*)(x + (size_t)row * D_);
    float4 v = xr[t];
    float s  = v.x + v.y + v.z + v.w;
    float s2 = v.x*v.x + v.y*v.y + v.z*v.z + v.w*v.w;
    #pragma unroll
    for (int o = 16; o > 0; o >>= 1) {
        s  += __shfl_xor_sync(0xffffffffu, s,  o);
        s2 += __shfl_xor_sync(0xffffffffu, s2, o);
    }
    __shared__ float rs[8], rs2[8];
    const int w = t >> 5;
    if ((t & 31) == 0) { rs[w] = s; rs2[w] = s2; }
    __syncthreads();
    s = 0.f; s2 = 0.f;
    #pragma unroll
    for (int i = 0; i < 8; i++) { s += rs[i]; s2 += rs2[i]; }
    const float mu   = s * (1.0f / D_);
    const float var  = s2 * (1.0f / D_) - mu * mu;
    const float rstd = rsqrtf(var + 1e-5f);
    float4 gg = ((const float4*)g)[t];
    float4 bb = ((const float4*)bta)[t];
    float4 o4;
    o4.x = (v.x - mu) * rstd * gg.x + bb.x;
    o4.y = (v.y - mu) * rstd * gg.y + bb.y;
    o4.z = (v.z - mu) * rstd * gg.z + bb.z;
    o4.w = (v.w - mu) * rstd * gg.w + bb.w;
    if (RND) {
        o4.x = to_tf32(o4.x); o4.y = to_tf32(o4.y);
        o4.z = to_tf32(o4.z); o4.w = to_tf32(o4.w);
    }
    ((float4*)(out + (size_t)row * D_))[t] = o4;
}

// ---------------- TF32 tensor-core GEMM-NT (mma.sync + ldmatrix) -------------
enum { EPI_NONE = 0, EPI_RES = 1, EPI_GELU = 2 };
#define GEMM_SMEM (2 * 32768)

template <int EPI>
__global__ __launch_bounds__(256) void gemm_mma(
    int M, int N, int K,
    const float* __restrict__ A, const float* __restrict__ Bw,
    const float* __restrict__ bias, const float* __restrict__ resid,
    float* __restrict__ C)
{
    extern __shared__ float sm[];   // [2][8192]: per buf: A 4096 floats, B 4096
    const int tid  = threadIdx.x;
    const int lane = tid & 31;
    const int wid  = tid >> 5;
    const int wm = wid & 1;
    const int wn = wid >> 1;
    const int brow = blockIdx.y * 128;
    const int bcol = blockIdx.x * 128;
    const int T = K >> 5;

    const uint32_t smb = smem_u32(sm);

    int am[4], akq[4];
    #pragma unroll
    for (int p = 0; p < 4; p++) {
        const int c = tid + 256 * p;
        am[p]  = c >> 3;
        akq[p] = c & 7;
    }

    float acc[4][4][4];
    #pragma unroll
    for (int mi = 0; mi < 4; mi++)
        #pragma unroll
        for (int ni = 0; ni < 4; ni++)
            #pragma unroll
            for (int e = 0; e < 4; e++) acc[mi][ni][e] = 0.f;

    auto issue = [&](int i, int bsel) {
        const uint32_t dA = smb + bsel * 32768u;
        const uint32_t dB = dA + 16384u;
        const int kbase = i * 32;
        #pragma unroll
        for (int p = 0; p < 4; p++) {
            const int m = am[p], kq = akq[p];
            const uint32_t doff = (uint32_t)(m * 128 + (((kq ^ (m & 7)) << 4)));
            cp16(dA + doff, A  + (size_t)(brow + m) * K + kbase + kq * 4);
            cp16(dB + doff, Bw + (size_t)(bcol + m) * K + kbase + kq * 4);
        }
        cp_commit();
    };

    // ldmatrix lane addressing (f32 index = row*32 + (k ^ ((row&7)<<2)))
    // A x4 tile at (m0,k0): mats = [(m0..+7,k0),(m0+8..,k0),(m0..,k0+4),(m0+8..,k0+4)]
    const int a_mb  = (lane & 7) + (((lane >> 3) & 1) << 3);  // row within m16
    const int a_kf  = (lane >> 4) << 2;                        // 0 or 4
    // B x4 tile: two ni tiles (16 n-rows), mats = [ni0 k0, ni0 k0+4, ni1 k0, ni1 k0+4]
    const int b_nb  = (lane & 7) + ((lane >> 4) << 3);         // row within n16
    const int b_kf  = ((lane >> 3) & 1) << 2;                  // 0 or 4
    const int xsh   = (lane & 7) << 2;                         // swizzle xor (same for A/B)
    uint32_t amrow[4], bnrow[2];
    #pragma unroll
    for (int mi = 0; mi < 4; mi++)
        amrow[mi] = (uint32_t)((wm * 64 + mi * 16 + a_mb) * 32);
    #pragma unroll
    for (int g = 0; g < 2; g++)
        bnrow[g] = (uint32_t)(4096 + (wn * 32 + g * 16 + b_nb) * 32);

    issue(0, 0);
    for (int i = 0; i < T; i++) {
        if (i + 1 < T) issue(i + 1, (i + 1) & 1);
        if (i + 1 < T) asm volatile("cp.async.wait_group 1;" ::: "memory");
        else           asm volatile("cp.async.wait_group 0;" ::: "memory");
        __syncthreads();

        const uint32_t bufb = smb + (uint32_t)(i & 1) * 32768u;

        #pragma unroll
        for (int s = 0; s < 4; s++) {
            const int k0 = s * 8;
            const uint32_t kA = (uint32_t)((k0 + a_kf) ^ xsh);
            const uint32_t kB = (uint32_t)((k0 + b_kf) ^ xsh);
            uint32_t af[4][4], bfr[2][4];
            #pragma unroll
            for (int mi = 0; mi < 4; mi++)
                ldsm4(af[mi], bufb + 4u * (amrow[mi] + kA));
            #pragma unroll
            for (int g = 0; g < 2; g++)
                ldsm4(bfr[g], bufb + 4u * (bnrow[g] + kB));
            #pragma unroll
            for (int mi = 0; mi < 4; mi++)
                #pragma unroll
                for (int ni = 0; ni < 4; ni++)
                    mma8(acc[mi][ni], af[mi][0], af[mi][1], af[mi][2], af[mi][3],
                         bfr[ni >> 1][(ni & 1) * 2], bfr[ni >> 1][(ni & 1) * 2 + 1]);
        }
        __syncthreads();
    }

    #pragma unroll
    for (int mi = 0; mi < 4; mi++) {
        #pragma unroll
        for (int ni = 0; ni < 4; ni++) {
            const int r0  = brow + wm * 64 + mi * 16 + (lane >> 2);
            const int col = bcol + wn * 32 + ni * 8 + 2 * (lane & 3);
            const float b0 = bias[col], b1 = bias[col + 1];
            float v[4] = { acc[mi][ni][0] + b0, acc[mi][ni][1] + b1,
                           acc[mi][ni][2] + b0, acc[mi][ni][3] + b1 };
            if (EPI == EPI_RES) {
                const float2 x0 = *(const float2*)&resid[(size_t)r0 * N + col];
                const float2 x1 = *(const float2*)&resid[(size_t)(r0 + 8) * N + col];
                v[0] += x0.x; v[1] += x0.y; v[2] += x1.x; v[3] += x1.y;
            }
            if (EPI == EPI_GELU) {
                #pragma unroll
                for (int e = 0; e < 4; e++) {
                    v[e] = 0.5f * v[e] * (1.0f + erff(v[e] * 0.70710678118654752f));
                    v[e] = to_tf32(v[e]);
                }
            }
            *(float2*)&C[(size_t)r0 * N + col]       = make_float2(v[0], v[1]);
            *(float2*)&C[(size_t)(r0 + 8) * N + col] = make_float2(v[2], v[3]);
        }
    }
}

// ---------------- tensor-core flash attention --------------------------------
__global__ __launch_bounds__(256) void attn_mma(
    const float* __restrict__ QKV, const int* __restrict__ mask,
    float* __restrict__ O)
{
    __shared__ __align__(16) float Ks[64][68];          // [key][dk] fp32
    __shared__ __align__(16) __nv_bfloat16 Vs[64][72];  // [dk][key] bf16

    const int b = blockIdx.z, h = blockIdx.y;
    const int tid = threadIdx.x, lane = tid & 31, wid = tid >> 5;
    const int gp = lane >> 2, tg = lane & 3;
    const int qrow0 = blockIdx.x * 128 + wid * 16 + gp;

    const float* Qb = QKV + (size_t)(b * S_) * QKV_S + h * DK_;
    const float* Kb = Qb + D_;
    const float* Vb = Qb + 2 * D_;

    uint32_t qf[8][4];
    {
        const float* q0p = Qb + (size_t)qrow0 * QKV_S;
        const float* q1p = q0p + (size_t)8 * QKV_S;
        #pragma unroll
        for (int s = 0; s < 8; s++) {
            qf[s][0] = __float_as_uint(q0p[tg + 8*s]     * 0.125f);
            qf[s][1] = __float_as_uint(q1p[tg + 8*s]     * 0.125f);
            qf[s][2] = __float_as_uint(q0p[tg + 8*s + 4] * 0.125f);
            qf[s][3] = __float_as_uint(q1p[tg + 8*s + 4] * 0.125f);
        }
    }

    float oa[8][4];
    #pragma unroll
    for (int j = 0; j < 8; j++)
        #pragma unroll
        for (int e = 0; e < 4; e++) oa[j][e] = 0.f;
    float m0c = -1e30f, m1c = -1e30f, l0 = 0.f, l1 = 0.f;

    const int* mr0 = mask + ((size_t)(b * S_ + qrow0)) * S_;
    const int* mr1 = mr0 + (size_t)8 * S_;

    for (int kt = 0; kt < S_; kt += 64) {
        #pragma unroll
        for (int p = 0; p < 4; p++) {
            const int c = tid + 256 * p;
            const int key = c >> 4, d4 = (c & 15) * 4;
            const size_t gk = (size_t)(kt + key) * QKV_S + d4;
            float4 k4 = *(const float4*)&Kb[gk];
            *(float4*)&Ks[key][d4] = k4;
            float4 v4 = *(const float4*)&Vb[gk];
            Vs[d4 + 0][key] = __float2bfloat16(v4.x);
            Vs[d4 + 1][key] = __float2bfloat16(v4.y);
            Vs[d4 + 2][key] = __float2bfloat16(v4.z);
            Vs[d4 + 3][key] = __float2bfloat16(v4.w);
        }
        __syncthreads();

        float sc[8][4];
        #pragma unroll
        for (int j = 0; j < 8; j++)
            #pragma unroll
            for (int e = 0; e < 4; e++) sc[j][e] = 0.f;
        #pragma unroll
        for (int s = 0; s < 8; s++) {
            #pragma unroll
            for (int j = 0; j < 8; j++) {
                const uint32_t kb0 = __float_as_uint(Ks[8*j + gp][tg + 8*s]);
                const uint32_t kb1 = __float_as_uint(Ks[8*j + gp][tg + 8*s + 4]);
                mma8(sc[j], qf[s][0], qf[s][1], qf[s][2], qf[s][3], kb0, kb1);
            }
        }

        #pragma unroll
        for (int j = 0; j < 8; j++) {
            const int2 mm0 = *(const int2*)&mr0[kt + 8*j + 2*tg];
            const int2 mm1 = *(const int2*)&mr1[kt + 8*j + 2*tg];
            if (mm0.x) sc[j][0] = -10000.0f;
            if (mm0.y) sc[j][1] = -10000.0f;
            if (mm1.x) sc[j][2] = -10000.0f;
            if (mm1.y) sc[j][3] = -10000.0f;
        }

        float t0 = -1e30f, t1 = -1e30f;
        #pragma unroll
        for (int j = 0; j < 8; j++) {
            t0 = fmaxf(t0, fmaxf(sc[j][0], sc[j][1]));
            t1 = fmaxf(t1, fmaxf(sc[j][2], sc[j][3]));
        }
        t0 = fmaxf(t0, __shfl_xor_sync(0xffffffffu, t0, 1));
        t0 = fmaxf(t0, __shfl_xor_sync(0xffffffffu, t0, 2));
        t1 = fmaxf(t1, __shfl_xor_sync(0xffffffffu, t1, 1));
        t1 = fmaxf(t1, __shfl_xor_sync(0xffffffffu, t1, 2));
        const float mn0 = fmaxf(m0c, t0), mn1 = fmaxf(m1c, t1);
        const float cr0 = __expf(m0c - mn0), cr1 = __expf(m1c - mn1);
        float ps0 = 0.f, ps1 = 0.f;
        #pragma unroll
        for (int j = 0; j < 8; j++) {
            sc[j][0] = __expf(sc[j][0] - mn0); ps0 += sc[j][0];
            sc[j][1] = __expf(sc[j][1] - mn0); ps0 += sc[j][1];
            sc[j][2] = __expf(sc[j][2] - mn1); ps1 += sc[j][2];
            sc[j][3] = __expf(sc[j][3] - mn1); ps1 += sc[j][3];
        }
        ps0 += __shfl_xor_sync(0xffffffffu, ps0, 1);
        ps0 += __shfl_xor_sync(0xffffffffu, ps0, 2);
        ps1 += __shfl_xor_sync(0xffffffffu, ps1, 1);
        ps1 += __shfl_xor_sync(0xffffffffu, ps1, 2);
        l0 = l0 * cr0 + ps0; m0c = mn0;
        l1 = l1 * cr1 + ps1; m1c = mn1;
        #pragma unroll
        for (int j = 0; j < 8; j++) {
            oa[j][0] *= cr0; oa[j][1] *= cr0;
            oa[j][2] *= cr1; oa[j][3] *= cr1;
        }

        uint32_t pa[4][4];
        #pragma unroll
        for (int t = 0; t < 4; t++) {
            pa[t][0] = bf16pk(sc[2*t][0],     sc[2*t][1]);
            pa[t][1] = bf16pk(sc[2*t][2],     sc[2*t][3]);
            pa[t][2] = bf16pk(sc[2*t + 1][0], sc[2*t + 1][1]);
            pa[t][3] = bf16pk(sc[2*t + 1][2], sc[2*t + 1][3]);
        }

        #pragma unroll
        for (int j = 0; j < 8; j++) {
            #pragma unroll
            for (int t = 0; t < 4; t++) {
                const uint32_t vb0 =
                    *(const uint32_t*)&Vs[8*j + gp][16*t + 2*tg];
                const uint32_t vb1 =
                    *(const uint32_t*)&Vs[8*j + gp][16*t + 8 + 2*tg];
                mma16bf(oa[j], pa[t], vb0, vb1);
            }
        }
        __syncthreads();
    }

    const float inv0 = 1.0f / l0, inv1 = 1.0f / l1;
    float* o0 = O + ((size_t)(b * S_ + qrow0)) * D_ + h * DK_;
    float* o1 = o0 + (size_t)8 * D_;
    #pragma unroll
    for (int j = 0; j < 8; j++) {
        *(float2*)&o0[8*j + 2*tg] =
            make_float2(to_tf32(oa[j][0] * inv0), to_tf32(oa[j][1] * inv0));
        *(float2*)&o1[8*j + 2*tg] =
            make_float2(to_tf32(oa[j][2] * inv1), to_tf32(oa[j][3] * inv1));
    }
}

// ---------------- launcher ----------------------------------------------------
extern "C" void kernel_launch(void* const* d_in, const int* in_sizes, int n_in,
                              void* d_out, int out_size)
{
    const float* x  = (const float*)d_in[0];
    const int*   mask = (const int*)d_in[1];
    const float* Wq = (const float*)d_in[2];  const float* bq = (const float*)d_in[3];
    const float* Wk = (const float*)d_in[4];  const float* bk = (const float*)d_in[5];
    const float* Wv = (const float*)d_in[6];  const float* bv = (const float*)d_in[7];
    const float* Wo = (const float*)d_in[8];  const float* bo = (const float*)d_in[9];
    const float* W1 = (const float*)d_in[10]; const float* b1 = (const float*)d_in[11];
    const float* W2 = (const float*)d_in[12]; const float* b2 = (const float*)d_in[13];
    const float* ga = (const float*)d_in[14]; const float* ba = (const float*)d_in[15];
    const float* gf = (const float*)d_in[16]; const float* bf = (const float*)d_in[17];
    float* out = (float*)d_out;

    float *nx, *x1, *qkv, *hb, *wqkv, *bqkv, *wo, *w1, *w2;
    cudaGetSymbolAddress((void**)&nx,   g_bufA);
    cudaGetSymbolAddress((void**)&x1,   g_x1);
    cudaGetSymbolAddress((void**)&qkv,  g_qkv);
    cudaGetSymbolAddress((void**)&hb,   g_h);
    cudaGetSymbolAddress((void**)&wqkv, g_wqkv);
    cudaGetSymbolAddress((void**)&bqkv, g_bqkv);
    cudaGetSymbolAddress((void**)&wo,   g_wo);
    cudaGetSymbolAddress((void**)&w1,   g_w1);
    cudaGetSymbolAddress((void**)&w2,   g_w2);

    cudaFuncSetAttribute(gemm_mma<EPI_NONE>,
                         cudaFuncAttributeMaxDynamicSharedMemorySize, GEMM_SMEM);
    cudaFuncSetAttribute(gemm_mma<EPI_RES>,
                         cudaFuncAttributeMaxDynamicSharedMemorySize, GEMM_SMEM);
    cudaFuncSetAttribute(gemm_mma<EPI_GELU>,
                         cudaFuncAttributeMaxDynamicSharedMemorySize, GEMM_SMEM);

    const int ndd4 = D_ * D_ / 4, ndf4 = DFF_ * D_ / 4;

    // launches 0..4: qkv weight cvt x3, bias pack, LN  -> launch #5 is the QKV GEMM
    cvt_tf32_kernel<<<(ndd4 + 255) / 256, 256>>>(Wq, wqkv,           ndd4);
    cvt_tf32_kernel<<<(ndd4 + 255) / 256, 256>>>(Wk, wqkv + D_*D_,   ndd4);
    cvt_tf32_kernel<<<(ndd4 + 255) / 256, 256>>>(Wv, wqkv + 2*D_*D_, ndd4);
    pack_bias_kernel<<<(D_ + 255) / 256, 256>>>(bq, bk, bv, bqkv);
    ln_kernel<1><<<ROWS, 256>>>(x, ga, ba, nx);

    // fused QKV projection (ncu -s 5 captures this launch)
    dim3 gqkv(QKV_S / 128, ROWS / 128);
    gemm_mma<EPI_NONE><<<gqkv, 256, GEMM_SMEM>>>(ROWS, QKV_S, D_, nx, wqkv, bqkv,
                                                 nullptr, qkv);

    // tensor-core flash attention (ctx -> nx, tf32-rounded)
    attn_mma<<<dim3(S_ / 128, H_, B_), 256>>>(qkv, mask, nx);

    // O-projection + residual -> x1
    cvt_tf32_kernel<<<(ndd4 + 255) / 256, 256>>>(Wo, wo, ndd4);
    dim3 g1(D_ / 128, ROWS / 128);
    gemm_mma<EPI_RES><<<g1, 256, GEMM_SMEM>>>(ROWS, D_, D_, nx, wo, bo, x, x1);

    // LN (ffn) -> nx2 (reuse qkv buffer)
    ln_kernel<1><<<ROWS, 256>>>(x1, gf, bf, qkv);

    // FFN1 + exact GELU
    cvt_tf32_kernel<<<(ndf4 + 255) / 256, 256>>>(W1, w1, ndf4);
    dim3 g2(DFF_ / 128, ROWS / 128);
    gemm_mma<EPI_GELU><<<g2, 256, GEMM_SMEM>>>(ROWS, DFF_, D_, qkv, w1, b1,
                                               nullptr, hb);

    // FFN2 + residual -> output
    cvt_tf32_kernel<<<(ndf4 + 255) / 256, 256>>>(W2, w2, ndf4);
    gemm_mma<EPI_RES><<<g1, 256, GEMM_SMEM>>>(ROWS, D_, DFF_, hb, w2, b2, x1, out);
}